// round 2
// baseline (speedup 1.0000x reference)
#include <cuda_runtime.h>
#include <math.h>

#define S1 1024
#define SN 1024
#define DV 64
#define KM 32
#define NPIX (S1*SN)

// ---------------- scratch (device globals; no allocations allowed) ----------
__device__ float g_v0[NPIX*DV];          // 268 MB ping
__device__ float g_v1[NPIX*DV];          // 268 MB pong
__device__ float g_Tre[KM*SN*DV];        // 8 MB
__device__ float g_Tim[KM*SN*DV];
__device__ float g_Gre[KM*KM*DV];        // 512 KB
__device__ float g_Gim[KM*KM*DV];
__device__ float g_G2re[KM*KM*DV];
__device__ float g_G2im[KM*KM*DV];
__device__ float g_Hre[S1*KM*DV];        // 8 MB
__device__ float g_Him[S1*KM*DV];
__device__ float g_tc[KM*1024];          // cos(2*pi*k*n/1024)
__device__ float g_ts[KM*1024];          // sin(2*pi*k*n/1024)

__device__ __forceinline__ float gelu_f(float x){
    return 0.5f * x * (1.0f + erff(x * 0.70710678118654752f));
}

// ---------------- twiddle tables --------------------------------------------
__global__ void k_twiddle(){
    int idx = blockIdx.x * blockDim.x + threadIdx.x;
    if (idx >= KM*1024) return;
    int k = idx >> 10, n = idx & 1023;
    int m = (k * n) & 1023;            // exact (k*n < 2^24)
    float s, c;
    sincospif((float)m * (1.0f/512.0f), &s, &c);   // angle = 2*pi*m/1024
    g_tc[idx] = c;
    g_ts[idx] = s;
}

// ---------------- shallow: v = gelu(input @ Wsh + bsh) ----------------------
__global__ __launch_bounds__(256) void k_shallow(const float* __restrict__ in,
                                                 const float* __restrict__ Wsh,
                                                 const float* __restrict__ bsh){
    int idx = blockIdx.x * 256 + threadIdx.x;     // over NPIX*DV
    int c = idx & 63;
    int p = idx >> 6;
    float x = fmaf(in[2*p], Wsh[c], fmaf(in[2*p+1], Wsh[DV+c], bsh[c]));
    g_v0[idx] = gelu_f(x);
}

// ---------------- fwd1: T[k1,y,c] = sum_x v[x,y,c] * e^{-2pi i k1 x / N} ----
// GEMM: M=32 (x2 for re/im), K=1024, N=65536 (n = y*64+c).
// block: 256 thr = 4 k-groups(8 k1 each) x 64 column-lanes (4 cols each) -> 256 cols/block
__global__ __launch_bounds__(256) void k_fwd1(int sel){
    const float* __restrict__ v = sel ? g_v1 : g_v0;
    __shared__ float sv[16][256];
    __shared__ float sc[16][32];
    __shared__ float ss[16][32];
    int t  = threadIdx.x;
    int kg = t >> 6;          // 0..3
    int cl = t & 63;          // column lane
    int colbase = blockIdx.x << 8;

    float aR[8][4], aI[8][4];
    #pragma unroll
    for (int k=0;k<8;k++)
        #pragma unroll
        for (int j=0;j<4;j++){ aR[k][j]=0.f; aI[k][j]=0.f; }

    for (int x0 = 0; x0 < S1; x0 += 16){
        #pragma unroll
        for (int i=0;i<16;i++)
            sv[i][t] = v[(x0+i)*65536 + colbase + t];
        #pragma unroll
        for (int i=t; i<512; i+=256){
            int xx = i >> 5, kk = i & 31;
            sc[xx][kk] = g_tc[kk*1024 + x0 + xx];
            ss[xx][kk] = g_ts[kk*1024 + x0 + xx];
        }
        __syncthreads();
        #pragma unroll 4
        for (int xx=0; xx<16; xx++){
            float4 v4 = *(const float4*)&sv[xx][cl<<2];
            #pragma unroll
            for (int k=0;k<8;k++){
                float c_ = sc[xx][(kg<<3)+k];
                float s_ = ss[xx][(kg<<3)+k];
                aR[k][0] = fmaf(v4.x, c_, aR[k][0]);
                aR[k][1] = fmaf(v4.y, c_, aR[k][1]);
                aR[k][2] = fmaf(v4.z, c_, aR[k][2]);
                aR[k][3] = fmaf(v4.w, c_, aR[k][3]);
                aI[k][0] = fmaf(-v4.x, s_, aI[k][0]);
                aI[k][1] = fmaf(-v4.y, s_, aI[k][1]);
                aI[k][2] = fmaf(-v4.z, s_, aI[k][2]);
                aI[k][3] = fmaf(-v4.w, s_, aI[k][3]);
            }
        }
        __syncthreads();
    }
    #pragma unroll
    for (int k=0;k<8;k++){
        int k1 = (kg<<3)+k;
        float4 r4 = make_float4(aR[k][0],aR[k][1],aR[k][2],aR[k][3]);
        float4 i4 = make_float4(aI[k][0],aI[k][1],aI[k][2],aI[k][3]);
        *(float4*)&g_Tre[k1*65536 + colbase + (cl<<2)] = r4;
        *(float4*)&g_Tim[k1*65536 + colbase + (cl<<2)] = i4;
    }
}

// ---------------- fwd2: G[k1,k2,c] = sum_y T[k1,y,c] * e^{-2pi i k2 y/N} ----
__global__ __launch_bounds__(256) void k_fwd2(){
    int k1 = blockIdx.x;
    int k2 = (blockIdx.y << 2) + (threadIdx.x >> 6);
    int c  = threadIdx.x & 63;
    const float* __restrict__ tr = g_Tre + k1*65536 + c;
    const float* __restrict__ ti = g_Tim + k1*65536 + c;
    const float* __restrict__ ec = g_tc + (k2<<10);
    const float* __restrict__ es = g_ts + (k2<<10);
    float ar = 0.f, ai = 0.f;
    #pragma unroll 4
    for (int y=0; y<1024; y++){
        float r = tr[y<<6], m = ti[y<<6];
        float cc = ec[y],  s = es[y];
        ar = fmaf(r, cc, fmaf(m,  s, ar));   // (Tr + iTi)(c - is): re
        ai = fmaf(m, cc, fmaf(-r, s, ai));   // im
    }
    int o = ((k1<<5)+k2)*64 + c;
    g_Gre[o] = ar;
    g_Gim[o] = ai;
}

// ---------------- R multiply: G2[.,d] = sum_c G[.,c]*(Rr+iRi)[.,c,d] --------
// folds the irfft weight (k2==0 ? 1 : 2)/N^2 into the output
__global__ __launch_bounds__(64) void k_rmul(const float* __restrict__ Rr,
                                             const float* __restrict__ Ri){
    int kk = blockIdx.x;              // k1*32+k2
    int d  = threadIdx.x;
    __shared__ float sgr[64], sgi[64];
    sgr[d] = g_Gre[kk*64 + d];
    sgi[d] = g_Gim[kk*64 + d];
    __syncthreads();
    const float* rr = Rr + kk*4096;
    const float* ri = Ri + kk*4096;
    float ar = 0.f, ai = 0.f;
    #pragma unroll 4
    for (int c=0;c<64;c++){
        float a = sgr[c], b = sgi[c];
        float x = rr[c*64 + d], y = ri[c*64 + d];
        ar = fmaf(a, x, fmaf(-b, y, ar));
        ai = fmaf(a, y, fmaf( b, x, ai));
    }
    int k2 = kk & 31;
    float scl = (k2 == 0 ? 1.0f : 2.0f) * (1.0f/1048576.0f);
    g_G2re[kk*64 + d] = ar * scl;
    g_G2im[kk*64 + d] = ai * scl;
}

// ---------------- inv1: H[x,k2,c] = sum_k1 G2[k1,k2,c]*e^{+2pi i k1 x/N} ----
// block covers 4 x values; thread owns 8 (k2,c) slots
__global__ __launch_bounds__(256) void k_inv1(){
    int t  = threadIdx.x;
    int x0 = blockIdx.x << 2;
    __shared__ float sc[4][32], ss[4][32];
    if (t < 128){
        int xx = t >> 5, kk = t & 31;
        sc[xx][kk] = g_tc[kk*1024 + x0 + xx];
        ss[xx][kk] = g_ts[kk*1024 + x0 + xx];
    }
    __syncthreads();
    float aR[4][8], aI[4][8];
    #pragma unroll
    for (int xx=0;xx<4;xx++)
        #pragma unroll
        for (int i=0;i<8;i++){ aR[xx][i]=0.f; aI[xx][i]=0.f; }

    for (int k1=0; k1<KM; k1++){
        float gr[8], gi[8];
        #pragma unroll
        for (int i=0;i<8;i++){
            gr[i] = g_G2re[k1*2048 + t + (i<<8)];
            gi[i] = g_G2im[k1*2048 + t + (i<<8)];
        }
        #pragma unroll
        for (int xx=0;xx<4;xx++){
            float c_ = sc[xx][k1], s_ = ss[xx][k1];
            #pragma unroll
            for (int i=0;i<8;i++){
                aR[xx][i] = fmaf(gr[i], c_, fmaf(-gi[i], s_, aR[xx][i]));
                aI[xx][i] = fmaf(gr[i], s_, fmaf( gi[i], c_, aI[xx][i]));
            }
        }
    }
    #pragma unroll
    for (int xx=0;xx<4;xx++)
        #pragma unroll
        for (int i=0;i<8;i++){
            g_Hre[(x0+xx)*2048 + t + (i<<8)] = aR[xx][i];
            g_Him[(x0+xx)*2048 + t + (i<<8)] = aI[xx][i];
        }
}

// ---------------- inv2 fused: out = gelu( irfft-part + v @ w ) --------------
// block: x fixed, 64-wide y tile; thread (ty,tc) owns 4y x 4c outputs
__global__ __launch_bounds__(256) void k_inv2(int sel, const float* __restrict__ w){
    const float* __restrict__ v   = sel ? g_v1 : g_v0;
    float*       __restrict__ out = sel ? g_v0 : g_v1;
    int x  = blockIdx.y;
    int y0 = blockIdx.x << 6;
    int t  = threadIdx.x;
    int tc = t & 15, ty = t >> 4;

    float acc[4][4];
    #pragma unroll
    for (int i=0;i<4;i++)
        #pragma unroll
        for (int j=0;j<4;j++) acc[i][j] = 0.f;

    // pointwise: acc[i][j] += sum_d v[x, y0+4ty+i, d] * w[d, 4tc+j]
    const float* vb = v + ((x<<10) + y0)*64;
    #pragma unroll 4
    for (int d=0; d<64; d+=4){
        float4 va[4];
        #pragma unroll
        for (int i=0;i<4;i++) va[i] = *(const float4*)&vb[((ty<<2)+i)*64 + d];
        float4 w0 = *(const float4*)&w[(d+0)*64 + (tc<<2)];
        float4 w1 = *(const float4*)&w[(d+1)*64 + (tc<<2)];
        float4 w2 = *(const float4*)&w[(d+2)*64 + (tc<<2)];
        float4 w3 = *(const float4*)&w[(d+3)*64 + (tc<<2)];
        #pragma unroll
        for (int i=0;i<4;i++){
            acc[i][0] = fmaf(va[i].x,w0.x,fmaf(va[i].y,w1.x,fmaf(va[i].z,w2.x,fmaf(va[i].w,w3.x,acc[i][0]))));
            acc[i][1] = fmaf(va[i].x,w0.y,fmaf(va[i].y,w1.y,fmaf(va[i].z,w2.y,fmaf(va[i].w,w3.y,acc[i][1]))));
            acc[i][2] = fmaf(va[i].x,w0.z,fmaf(va[i].y,w1.z,fmaf(va[i].z,w2.z,fmaf(va[i].w,w3.z,acc[i][2]))));
            acc[i][3] = fmaf(va[i].x,w0.w,fmaf(va[i].y,w1.w,fmaf(va[i].z,w2.w,fmaf(va[i].w,w3.w,acc[i][3]))));
        }
    }

    // spectral: acc[i][j] += sum_k2 Hre*cos - Him*sin   (weights already folded)
    const float* hr = g_Hre + x*2048;
    const float* hi = g_Him + x*2048;
    #pragma unroll 4
    for (int k2=0; k2<32; k2++){
        float4 r4 = *(const float4*)&hr[(k2<<6) + (tc<<2)];
        float4 i4 = *(const float4*)&hi[(k2<<6) + (tc<<2)];
        float4 c4 = *(const float4*)&g_tc[(k2<<10) + y0 + (ty<<2)];
        float4 s4 = *(const float4*)&g_ts[(k2<<10) + y0 + (ty<<2)];
        float rr[4] = {r4.x,r4.y,r4.z,r4.w};
        float ii[4] = {i4.x,i4.y,i4.z,i4.w};
        float cc[4] = {c4.x,c4.y,c4.z,c4.w};
        float sn[4] = {s4.x,s4.y,s4.z,s4.w};
        #pragma unroll
        for (int i=0;i<4;i++)
            #pragma unroll
            for (int j=0;j<4;j++)
                acc[i][j] = fmaf(rr[j], cc[i], fmaf(-ii[j], sn[i], acc[i][j]));
    }

    #pragma unroll
    for (int i=0;i<4;i++){
        float4 o;
        o.x = gelu_f(acc[i][0]);
        o.y = gelu_f(acc[i][1]);
        o.z = gelu_f(acc[i][2]);
        o.w = gelu_f(acc[i][3]);
        *(float4*)&out[((x<<10) + y0 + (ty<<2) + i)*64 + (tc<<2)] = o;
    }
}

// ---------------- projection: out[x,y] = v . Wp + bp ------------------------
__global__ __launch_bounds__(256) void k_proj(int sel, const float* __restrict__ Wp,
                                              const float* __restrict__ bp,
                                              float* __restrict__ out){
    const float* __restrict__ v = sel ? g_v1 : g_v0;
    int gw   = (blockIdx.x * 256 + threadIdx.x) >> 5;   // point index
    int lane = threadIdx.x & 31;
    const float* vp = v + gw*64;
    float s = fmaf(vp[lane], Wp[lane], vp[lane+32]*Wp[lane+32]);
    #pragma unroll
    for (int o=16;o;o>>=1) s += __shfl_down_sync(0xffffffffu, s, o);
    if (lane == 0) out[gw] = s + bp[0];
}

// ---------------- launcher --------------------------------------------------
extern "C" void kernel_launch(void* const* d_in, const int* in_sizes, int n_in,
                              void* d_out, int out_size){
    const float* input = (const float*)d_in[0];
    const float* Wsh   = (const float*)d_in[1];
    const float* bsh   = (const float*)d_in[2];
    const float* Rr[4] = {(const float*)d_in[3],(const float*)d_in[6],
                          (const float*)d_in[9],(const float*)d_in[12]};
    const float* Ri[4] = {(const float*)d_in[4],(const float*)d_in[7],
                          (const float*)d_in[10],(const float*)d_in[13]};
    const float* ww[4] = {(const float*)d_in[5],(const float*)d_in[8],
                          (const float*)d_in[11],(const float*)d_in[14]};
    const float* Wp = (const float*)d_in[15];
    const float* bp = (const float*)d_in[16];
    float* out = (float*)d_out;

    k_twiddle<<<128, 256>>>();
    k_shallow<<<(NPIX*DV)/256, 256>>>(input, Wsh, bsh);

    int cur = 0;   // g_v0 holds current activation
    for (int l=0; l<4; l++){
        k_fwd1<<<256, 256>>>(cur);
        k_fwd2<<<dim3(32,8), 256>>>();
        k_rmul<<<1024, 64>>>(Rr[l], Ri[l]);
        k_inv1<<<256, 256>>>();
        k_inv2<<<dim3(16,1024), 256>>>(cur, ww[l]);
        cur ^= 1;
    }
    k_proj<<<NPIX/8, 256>>>(cur, Wp, bp, out);
}